// round 13
// baseline (speedup 1.0000x reference)
#include <cuda_runtime.h>
#include <cstdint>
#include <cstddef>

// out[n, l, o] = weight[o, l]   for n in [0,128), l,o in [0,1024)
// 512 MB broadcast-write of weight.T.
// Round 13 mechanism change: bulk-async stores (cp.async.bulk smem->gmem).
//  - bypasses the per-warp L1tex store path (was at 82% duty in R12)
//  - each op writes a 32KB CONTIGUOUS gmem region -> large sequential DRAM
//    write bursts instead of interleaved 128B warp segments.
// Block: gather weight[:, l0:l0+8] (L2-resident), transpose to linear smem
// tile (8 rows x 4KB), issue 4 bulk stores (one per plane), wait, exit.

namespace {
constexpr int L   = 1024;
constexpr int OUT = 1024;
constexpr int N   = 128;

constexpr int TLROWS = 8;                        // l-rows per tile
constexpr int TILE_BYTES = TLROWS * OUT * 4;     // 32 KB contiguous
constexpr int NZ = 32;                           // plane split
constexpr int N_PER_BLOCK = N / NZ;              // 4 bulk stores per block
constexpr int THREADS = 256;
}

__global__ __launch_bounds__(THREADS)
void lfd_bulkstore(const float* __restrict__ w,
                   float* __restrict__ out) {
    // Linear tile: tile[l][o] = weight[o][l0+l]; exactly the gmem image of
    // out-plane rows l0..l0+7 (contiguous 32 KB).
    __shared__ __align__(16) float tile[TLROWS][OUT];

    const int l0 = blockIdx.x * TLROWS;
    const int n0 = blockIdx.y * N_PER_BLOCK;
    const int tid = threadIdx.x;

    // ---- Gather column strip weight[:, l0:l0+8] and transpose into smem ----
    // Each thread handles 4 o-rows; per row: two float4 = 8 floats (l0..l0+7).
    // 4 KB-strided gather (one 32B sector per o-row) -> L2 hits after wave 1.
#pragma unroll
    for (int k = 0; k < 4; k++) {
        const int o = tid + k * THREADS;          // 0..1023
        const float4 a = *reinterpret_cast<const float4*>(&w[(size_t)o * L + l0]);
        const float4 b = *reinterpret_cast<const float4*>(&w[(size_t)o * L + l0 + 4]);
        tile[0][o] = a.x; tile[1][o] = a.y; tile[2][o] = a.z; tile[3][o] = a.w;
        tile[4][o] = b.x; tile[5][o] = b.y; tile[6][o] = b.z; tile[7][o] = b.w;
    }
    __syncthreads();

    // ---- Bulk-async stores: one 32KB contiguous op per plane ----
    if (tid == 0) {
        asm volatile("fence.proxy.async.shared::cta;" ::: "memory");
        uint32_t saddr = (uint32_t)__cvta_generic_to_shared(&tile[0][0]);
        const size_t plane = (size_t)L * OUT;
        size_t base = (size_t)n0 * plane + (size_t)l0 * OUT;
#pragma unroll
        for (int n = 0; n < N_PER_BLOCK; n++) {
            asm volatile(
                "cp.async.bulk.global.shared::cta.bulk_group [%0], [%1], %2;"
                :: "l"(out + base), "r"(saddr), "r"((int)TILE_BYTES)
                : "memory");
            base += plane;
        }
        asm volatile("cp.async.bulk.commit_group;" ::: "memory");
        asm volatile("cp.async.bulk.wait_group 0;" ::: "memory");
    }
    // CTA (and its smem) stays alive until all threads exit; tid 0's wait
    // guarantees the bulk reads of smem have completed by then.
}

extern "C" void kernel_launch(void* const* d_in, const int* in_sizes, int n_in,
                              void* d_out, int out_size) {
    // d_in[0] = x (unused — reference discards net(x)), d_in[1] = weight [1024,1024]
    const float* weight = (const float*)d_in[1];
    float* out = (float*)d_out;

    dim3 grid(L / TLROWS, NZ);        // (128, 32) = 4096 blocks
    lfd_bulkstore<<<grid, THREADS>>>(weight, out);
}

// round 14
// speedup vs baseline: 1.1376x; 1.1376x over previous
#include <cuda_runtime.h>
#include <cstdint>
#include <cstddef>

// out[n, l, o] = weight[o, l]   for n in [0,128), l,o in [0,1024)
// 512 MB broadcast-write of weight.T; smem transpose -> register -> __stcs
// replicate-stores. Mechanism space mapped: LSU __stcs wins over TMA-store,
// write-through, default/split policy, and two-kernel copy.
// Round 14 convergence probe: compose the best-performing corners —
//   32768 blocks (R8 granularity) x 8 STG/thread (R7 amortization)
//   x 128 threads / 4-warp barrier x TL=16 (short tile latency chain).

namespace {
constexpr int L   = 1024;
constexpr int OUT = 1024;
constexpr int N   = 128;

constexpr int TL = 16;   // tile extent along l
constexpr int TO = 32;   // tile extent along o
constexpr int NZ = 16;   // grid (64,32,16) = 32768 blocks
constexpr int N_PER_BLOCK = N / NZ;  // 8 planes per block -> 8 STG/thread
constexpr int THREADS = 128;
}

__global__ __launch_bounds__(THREADS)
void linfwddiff_bcast_conv(const float* __restrict__ w,
                           float* __restrict__ out) {
    // Padded transpose tile: tile[l][o]; row stride 36 floats (no bank conflicts).
    __shared__ __align__(16) float tile[TL][TO + 4];

    const int l0 = blockIdx.x * TL;
    const int o0 = blockIdx.y * TO;
    const int n0 = blockIdx.z * N_PER_BLOCK;
    const int tid = threadIdx.x;

    // ---- Load weight tile [o0:o0+32, l0:l0+16], transposing into smem ----
    // 32 rows (o) x 4 float4 (l) = 128 slots; 1 per thread.
    {
        const int r = tid >> 2;       // o offset within tile: 0..31
        const int c = tid & 3;        // l float4 column:      0..3
        const float4 v = *reinterpret_cast<const float4*>(
            &w[(size_t)(o0 + r) * L + l0 + c * 4]);
        tile[c * 4 + 0][r] = v.x;
        tile[c * 4 + 1][r] = v.y;
        tile[c * 4 + 2][r] = v.z;
        tile[c * 4 + 3][r] = v.w;
    }
    __syncthreads();

    // ---- Hoist transposed values into registers (1 float4 per thread) ----
    // 16 rows (l) x 8 float4 (o) = 128 slots; 1 per thread.
    const int l_a = tid >> 3;         // l within tile: 0..15
    const int c_a = tid & 7;          // o float4 column: 0..7
    const float4 va = *reinterpret_cast<const float4*>(&tile[l_a][c_a * 4]);

    const size_t plane = (size_t)L * OUT;                       // 1M elements
    const size_t offa = (size_t)(l0 + l_a) * OUT + o0 + c_a * 4;
    size_t base = (size_t)n0 * plane;

    // ---- Replicate-store across n: pure STG.128 stream, evict-first ----
#pragma unroll
    for (int n = 0; n < N_PER_BLOCK; n++) {
        __stcs(reinterpret_cast<float4*>(&out[base + offa]), va);
        base += plane;
    }
}

extern "C" void kernel_launch(void* const* d_in, const int* in_sizes, int n_in,
                              void* d_out, int out_size) {
    // d_in[0] = x (unused — reference discards net(x)), d_in[1] = weight [1024,1024]
    const float* weight = (const float*)d_in[1];
    float* out = (float*)d_out;

    dim3 grid(L / TL, OUT / TO, NZ);   // (64, 32, 16) = 32768 blocks
    linfwddiff_bcast_conv<<<grid, THREADS>>>(weight, out);
}

// round 15
// speedup vs baseline: 1.1731x; 1.0312x over previous
#include <cuda_runtime.h>
#include <cstdint>
#include <cstddef>

// FINAL: out[n, l, o] = weight[o, l]  for n in [0,128), l,o in [0,1024)
//
// The reference einsum('nlk,ok->nlo', eye(L), weight) collapses to a 512 MB
// broadcast-write of weight.T (x is discarded). This kernel is the measured
// optimum of the explored space:
//  - smem transpose of a 32x32 weight tile -> registers (1 float4/thread)
//  - __stcs evict-first STG.128 replicate-stores across 4 n-planes/block
//  - grid (32,32,32) = 32768 fine-grained blocks for scheduler backfill
// Measured: 73.7 us kernel, DRAM 82.4% duty / 6.53 TB/s — the empirical
// HBM3e pure-write ceiling. Falsified alternatives: TMA bulk-store (-19%),
// write-through (-12%), default/split L2 policy (-9%/0%), two-kernel copy
// (-21%), single-wave launch (-8%), finer granularity w/ 2 STG/thr (-17%).

namespace {
constexpr int L   = 1024;
constexpr int OUT = 1024;
constexpr int N   = 128;

constexpr int TL = 32;   // tile extent along l
constexpr int TO = 32;   // tile extent along o
constexpr int NZ = 32;   // grid (32,32,32) = 32768 blocks
constexpr int N_PER_BLOCK = N / NZ;  // 4 planes per block
constexpr int THREADS = 256;
}

__global__ __launch_bounds__(THREADS)
void linfwddiff_final(const float* __restrict__ w,
                      float* __restrict__ out) {
    // Padded transpose tile: tile[l][o]; row stride 36 floats (no bank conflicts).
    __shared__ __align__(16) float tile[TL][TO + 4];

    const int l0 = blockIdx.x * TL;
    const int o0 = blockIdx.y * TO;
    const int n0 = blockIdx.z * N_PER_BLOCK;
    const int tid = threadIdx.x;

    // ---- Load weight tile [o0:o0+32, l0:l0+32], transposing into smem ----
    // 32 rows (o) x 8 float4 (l) = 256 slots; 1 per thread.
    {
        const int r = tid >> 3;       // o offset within tile: 0..31
        const int c = tid & 7;        // l float4 column:      0..7
        const float4 v = *reinterpret_cast<const float4*>(
            &w[(size_t)(o0 + r) * L + l0 + c * 4]);
        tile[c * 4 + 0][r] = v.x;
        tile[c * 4 + 1][r] = v.y;
        tile[c * 4 + 2][r] = v.z;
        tile[c * 4 + 3][r] = v.w;
    }
    __syncthreads();

    // ---- Hoist transposed values into registers (1 float4 per thread) ----
    // 32 rows (l) x 8 float4 (o) = 256 slots; 1 per thread.
    const int l_a = tid >> 3;         // l within tile: 0..31
    const int c_a = tid & 7;          // o float4 column: 0..7
    const float4 va = *reinterpret_cast<const float4*>(&tile[l_a][c_a * 4]);

    const size_t plane = (size_t)L * OUT;                       // 1M elements
    const size_t offa = (size_t)(l0 + l_a) * OUT + o0 + c_a * 4;
    size_t base = (size_t)n0 * plane;

    // ---- Replicate-store across n: pure STG.128 stream, evict-first ----
#pragma unroll
    for (int n = 0; n < N_PER_BLOCK; n++) {
        __stcs(reinterpret_cast<float4*>(&out[base + offa]), va);
        base += plane;
    }
}

extern "C" void kernel_launch(void* const* d_in, const int* in_sizes, int n_in,
                              void* d_out, int out_size) {
    // d_in[0] = x (unused — reference discards net(x)), d_in[1] = weight [1024,1024]
    const float* weight = (const float*)d_in[1];
    float* out = (float*)d_out;

    dim3 grid(L / TL, OUT / TO, NZ);   // (32, 32, 32) = 32768 blocks
    linfwddiff_final<<<grid, THREADS>>>(weight, out);
}